// round 2
// baseline (speedup 1.0000x reference)
#include <cuda_runtime.h>
#include <cstdint>

#define EMB   128
#define NQ    32
#define TILE  128
#define WPAD  129
#define NBLK  296
#define NWARP 4
#define TOPK  10

#define NEG_HUGE (-3.402823466e38f)

// scratch (no cudaMalloc allowed)
__device__ float g_qnT[EMB * NQ];                      // normalized queries, [k][q]
__device__ float g_cv[NBLK * NWARP * NQ * TOPK];       // per-warp candidate values
__device__ int   g_ci[NBLK * NWARP * NQ * TOPK];       // per-warp candidate indices

// ---------------------------------------------------------------------------
// Kernel 0: normalize queries, store transposed [k][q] for broadcast reads
// ---------------------------------------------------------------------------
__global__ void normq_kernel(const float* __restrict__ q) {
    int qi = blockIdx.x;      // 0..31
    int d  = threadIdx.x;     // 0..127
    float v  = q[qi * EMB + d];
    float ss = v * v;
    #pragma unroll
    for (int o = 16; o > 0; o >>= 1) ss += __shfl_xor_sync(0xffffffffu, ss, o);
    __shared__ float ws[4];
    if ((d & 31) == 0) ws[d >> 5] = ss;
    __syncthreads();
    float tot = ws[0] + ws[1] + ws[2] + ws[3];
    float inv = 1.0f / fmaxf(sqrtf(tot), 1e-12f);
    g_qnT[d * NQ + qi] = v * inv;
}

// ---------------------------------------------------------------------------
// Kernel 1: fused scores + per-warp block-local top-10
// Block: 128 threads = 4 warps. Warp ty owns queries [8ty, 8ty+8).
// Thread (tx,ty): 8 queries x 4 rows (rows tx, tx+32, tx+64, tx+96 of tile).
// ---------------------------------------------------------------------------

#define FMA2(a, b, c) asm("fma.rn.f32x2 %0, %1, %2, %0;" : "+l"(a) : "l"(b), "l"(c))
#define PACK2(d, f)   asm("mov.b64 %0, {%1, %2};" : "=l"(d) : "r"(__float_as_uint(f)), "r"(__float_as_uint(f)))

#define INSERT(sval, qq, rr) do {                                              \
    bool cnd = ((sval) > thr[(qq)]) && (gbase + tx + 32 * (rr) < n);           \
    unsigned m = __ballot_sync(0xffffffffu, cnd);                              \
    while (m) {                                                                \
        int src = __ffs(m) - 1; m &= m - 1;                                    \
        float v = __shfl_sync(0xffffffffu, (sval), src);                       \
        if (v > thr[(qq)]) {                                                   \
            int gi = gbase + src + 32 * (rr);                                  \
            int qg = ty * 8 + (qq);                                            \
            float* lv = &wv[(ty * NQ + qg) * TOPK];                            \
            int*   li = &wi[(ty * NQ + qg) * TOPK];                            \
            float mn = lv[0]; int ms = 0;                                      \
            _Pragma("unroll")                                                  \
            for (int j = 1; j < TOPK; j++) { float t = lv[j]; if (t < mn) { mn = t; ms = j; } } \
            lv[ms] = v; li[ms] = gi;                                           \
            float nt = lv[0];                                                  \
            _Pragma("unroll")                                                  \
            for (int j = 1; j < TOPK; j++) nt = fminf(nt, lv[j]);              \
            thr[(qq)] = nt;                                                    \
        }                                                                      \
    }                                                                          \
} while (0)

__global__ __launch_bounds__(128, 2)
void score_topk_kernel(const float* __restrict__ corpus, int n, int nTiles) {
    extern __shared__ float smem[];
    float* sct  = smem;                        // TILE * WPAD  (row-major, pad 1)
    float* qsm  = sct + TILE * WPAD;           // EMB * NQ     ([k][q])
    float* sinv = qsm + EMB * NQ;              // TILE
    float* wv   = sinv + TILE;                 // NWARP*NQ*TOPK
    int*   wi   = (int*)(wv + NWARP * NQ * TOPK);

    int tid = threadIdx.x;
    int tx  = tid & 31;
    int ty  = tid >> 5;

    for (int i = tid; i < EMB * NQ; i += 128) qsm[i] = g_qnT[i];
    #pragma unroll
    for (int s = 0; s < TOPK; s++) {
        wv[(ty * NQ + tx) * TOPK + s] = NEG_HUGE;
        wi[(ty * NQ + tx) * TOPK + s] = 0;
    }
    float thr[8];
    #pragma unroll
    for (int j = 0; j < 8; j++) thr[j] = NEG_HUGE;
    __syncthreads();

    const float4* c4p = (const float4*)corpus;

    for (int tile = blockIdx.x; tile < nTiles; tile += gridDim.x) {
        int gbase = tile * TILE;

        // ---- stage tile + row norms (warp covers exactly one row per step) ----
        #pragma unroll 8
        for (int i = 0; i < 32; i++) {
            int idx = tid + 128 * i;
            int row = idx >> 5, c4 = idx & 31;
            int g   = gbase + row;
            float4 v = (g < n) ? c4p[(size_t)g * 32 + c4]
                               : make_float4(0.f, 0.f, 0.f, 0.f);
            int so = row * WPAD + c4 * 4;
            sct[so + 0] = v.x; sct[so + 1] = v.y;
            sct[so + 2] = v.z; sct[so + 3] = v.w;
            float ss = v.x * v.x + v.y * v.y + v.z * v.z + v.w * v.w;
            #pragma unroll
            for (int o = 16; o > 0; o >>= 1) ss += __shfl_xor_sync(0xffffffffu, ss, o);
            if (tx == 0) sinv[row] = 1.0f / fmaxf(sqrtf(ss), 1e-12f);
        }
        __syncthreads();

        // ---- register-tiled GEMM, all math as packed f32x2 ----
        unsigned long long acc[4][4];
        #pragma unroll
        for (int a = 0; a < 4; a++)
            #pragma unroll
            for (int b = 0; b < 4; b++) acc[a][b] = 0ull;

        #pragma unroll 8
        for (int k = 0; k < EMB; k++) {
            const unsigned long long* qp =
                (const unsigned long long*)(qsm + k * NQ + ty * 8);
            unsigned long long q0 = qp[0], q1 = qp[1], q2 = qp[2], q3 = qp[3];
            float c0 = sct[(tx +  0) * WPAD + k];
            float c1 = sct[(tx + 32) * WPAD + k];
            float c2 = sct[(tx + 64) * WPAD + k];
            float c3 = sct[(tx + 96) * WPAD + k];
            unsigned long long d0, d1, d2, d3;
            PACK2(d0, c0); PACK2(d1, c1); PACK2(d2, c2); PACK2(d3, c3);
            FMA2(acc[0][0], q0, d0); FMA2(acc[0][1], q0, d1);
            FMA2(acc[0][2], q0, d2); FMA2(acc[0][3], q0, d3);
            FMA2(acc[1][0], q1, d0); FMA2(acc[1][1], q1, d1);
            FMA2(acc[1][2], q1, d2); FMA2(acc[1][3], q1, d3);
            FMA2(acc[2][0], q2, d0); FMA2(acc[2][1], q2, d1);
            FMA2(acc[2][2], q2, d2); FMA2(acc[2][3], q2, d3);
            FMA2(acc[3][0], q3, d0); FMA2(acc[3][1], q3, d1);
            FMA2(acc[3][2], q3, d2); FMA2(acc[3][3], q3, d3);
        }

        // ---- epilogue: scale by corpus inv-norm, threshold + insert ----
        float cinv[4];
        cinv[0] = sinv[tx +  0]; cinv[1] = sinv[tx + 32];
        cinv[2] = sinv[tx + 64]; cinv[3] = sinv[tx + 96];
        #pragma unroll
        for (int qp2 = 0; qp2 < 4; qp2++) {
            #pragma unroll
            for (int rr = 0; rr < 4; rr++) {
                unsigned lo = (unsigned)(acc[qp2][rr] & 0xffffffffull);
                unsigned hi = (unsigned)(acc[qp2][rr] >> 32);
                float s0 = __uint_as_float(lo) * cinv[rr];
                float s1 = __uint_as_float(hi) * cinv[rr];
                INSERT(s0, 2 * qp2 + 0, rr);
                INSERT(s1, 2 * qp2 + 1, rr);
            }
        }
        __syncthreads();   // protect sct/sinv before next tile's stores
    }

    // ---- dump per-warp lists to global candidate buffer ----
    int base = ((blockIdx.x * NWARP + ty) * NQ + tx) * TOPK;
    #pragma unroll
    for (int s = 0; s < TOPK; s++) {
        g_cv[base + s] = wv[(ty * NQ + tx) * TOPK + s];
        g_ci[base + s] = wi[(ty * NQ + tx) * TOPK + s];
    }
}

// ---------------------------------------------------------------------------
// Kernel 2: merge NBLK*NWARP*TOPK candidates per query -> final sorted top-10
// ---------------------------------------------------------------------------
__global__ void merge_kernel(float* __restrict__ out, int out_size) {
    int q   = blockIdx.x;     // 0..31
    int tid = threadIdx.x;    // 0..255
    const int NC = NBLK * NWARP * TOPK;

    float lv[TOPK]; int li[TOPK];
    #pragma unroll
    for (int j = 0; j < TOPK; j++) { lv[j] = NEG_HUGE; li[j] = 0x7fffffff; }
    for (int t = tid; t < NC; t += 256) {
        int outer = t / TOPK, s = t % TOPK;
        float v = g_cv[(outer * NQ + q) * TOPK + s];
        int  gi = g_ci[(outer * NQ + q) * TOPK + s];
        float mn = lv[0]; int ms = 0;
        #pragma unroll
        for (int j = 1; j < TOPK; j++) if (lv[j] < mn) { mn = lv[j]; ms = j; }
        if (v > mn) { lv[ms] = v; li[ms] = gi; }
    }

    __shared__ float sv[256 * TOPK];
    __shared__ int   si[256 * TOPK];
    #pragma unroll
    for (int j = 0; j < TOPK; j++) { sv[tid * TOPK + j] = lv[j]; si[tid * TOPK + j] = li[j]; }
    __syncthreads();

    __shared__ float fv[32 * TOPK];
    __shared__ int   fi[32 * TOPK];
    if (tid < 32) {
        float l2[TOPK]; int i2[TOPK];
        #pragma unroll
        for (int j = 0; j < TOPK; j++) { l2[j] = NEG_HUGE; i2[j] = 0x7fffffff; }
        for (int t = tid; t < 256 * TOPK; t += 32) {
            float v = sv[t]; int gi = si[t];
            float mn = l2[0]; int ms = 0;
            #pragma unroll
            for (int j = 1; j < TOPK; j++) if (l2[j] < mn) { mn = l2[j]; ms = j; }
            if (v > mn) { l2[ms] = v; i2[ms] = gi; }
        }
        #pragma unroll
        for (int j = 0; j < TOPK; j++) { fv[tid * TOPK + j] = l2[j]; fi[tid * TOPK + j] = i2[j]; }
    }
    __syncthreads();

    if (tid == 0) {
        float l3[TOPK]; int i3[TOPK];
        #pragma unroll
        for (int j = 0; j < TOPK; j++) { l3[j] = NEG_HUGE; i3[j] = 0x7fffffff; }
        for (int t = 0; t < 32 * TOPK; t++) {
            float v = fv[t]; int gi = fi[t];
            float mn = l3[0]; int ms = 0;
            #pragma unroll
            for (int j = 1; j < TOPK; j++) if (l3[j] < mn) { mn = l3[j]; ms = j; }
            if (v > mn) { l3[ms] = v; i3[ms] = gi; }
        }
        // selection sort desc, tie -> lower index first (matches lax.top_k)
        for (int a = 0; a < TOPK; a++) {
            int best = a;
            for (int b = a + 1; b < TOPK; b++)
                if (l3[b] > l3[best] ||
                    (l3[b] == l3[best] && i3[b] < i3[best])) best = b;
            float tv = l3[a]; l3[a] = l3[best]; l3[best] = tv;
            int   ti = i3[a]; i3[a] = i3[best]; i3[best] = ti;
        }
        // output: scores [32*TOPK] then indices-as-float [32*TOPK]
        if (out_size >= 2 * NQ * TOPK) {
            for (int j = 0; j < TOPK; j++) {
                out[q * TOPK + j] = l3[j];
                out[NQ * TOPK + q * TOPK + j] = (float)i3[j];
            }
        } else {
            for (int j = 0; j < TOPK; j++)
                if (q * TOPK + j < out_size) out[q * TOPK + j] = l3[j];
        }
    }
}

// ---------------------------------------------------------------------------
extern "C" void kernel_launch(void* const* d_in, const int* in_sizes, int n_in,
                              void* d_out, int out_size) {
    const float* queries = (const float*)d_in[0];
    const float* corpus  = (const float*)d_in[1];
    int n = in_sizes[1] / EMB;
    int nTiles = (n + TILE - 1) / TILE;

    size_t smemBytes = (size_t)(TILE * WPAD + EMB * NQ + TILE + NWARP * NQ * TOPK) * sizeof(float)
                     + (size_t)(NWARP * NQ * TOPK) * sizeof(int);
    cudaFuncSetAttribute(score_topk_kernel,
                         cudaFuncAttributeMaxDynamicSharedMemorySize, (int)smemBytes);

    normq_kernel<<<NQ, EMB>>>(queries);
    score_topk_kernel<<<NBLK, 128, smemBytes>>>(corpus, n, nTiles);
    merge_kernel<<<NQ, 256>>>((float*)d_out, out_size);
}

// round 3
// speedup vs baseline: 1.4561x; 1.4561x over previous
#include <cuda_runtime.h>
#include <cstdint>

#define EMB   128
#define NQ    32
#define TILE  64
#define WPAD  132          // floats per row; 132%32=4 -> conflict-free LDS.128
#define W4    33           // WPAD/4
#define NBLK  296
#define TOPK  10
#define NEG_HUGE (-3.402823466e38f)

// persistent scratch (no cudaMalloc allowed)
__device__ float    g_cv[NBLK * 4 * 8 * TOPK];   // per (block,warp,query) candidates
__device__ int      g_ci[NBLK * 4 * 8 * TOPK];
__device__ unsigned g_ctr = 0;                   // wraps back to 0 every launch

#define FMA2(a, b, c) asm("fma.rn.f32x2 %0, %1, %2, %0;" : "+l"(a) : "l"(b), "l"(c))
#define PACK2(d, x, y) asm("mov.b64 %0, {%1, %2};" : "=l"(d) \
                           : "r"(__float_as_uint(x)), "r"(__float_as_uint(y)))
#define CP_ASYNC16(dst, src, sz) \
    asm volatile("cp.async.cg.shared.global [%0], [%1], 16, %2;\n" \
                 :: "r"(dst), "l"(src), "r"(sz))
#define CP_COMMIT()  asm volatile("cp.async.commit_group;\n" ::: "memory")
#define CP_WAIT1()   asm volatile("cp.async.wait_group 1;\n" ::: "memory")

// warp-cooperative top-10 insert; list lives in smem, thr warp-uniform per query
#define INSERT(sval, qq, rr) do {                                              \
    bool cnd = ((sval) > thr[(qq)]) && (gbase + tx + 32 * (rr) < n);           \
    unsigned m = __ballot_sync(0xffffffffu, cnd);                              \
    while (m) {                                                                \
        int src = __ffs(m) - 1; m &= m - 1;                                    \
        float v = __shfl_sync(0xffffffffu, (sval), src);                       \
        if (v > thr[(qq)]) {                                                   \
            int gi = gbase + src + 32 * (rr);                                  \
            float* lv = &wv[(ty * 8 + (qq)) * TOPK];                           \
            int*   li = &wi[(ty * 8 + (qq)) * TOPK];                           \
            float mn = lv[0]; int ms = 0;                                      \
            _Pragma("unroll")                                                  \
            for (int j = 1; j < TOPK; j++) { float t = lv[j]; if (t < mn) { mn = t; ms = j; } } \
            lv[ms] = v; li[ms] = gi;                                           \
            float nt = lv[0];                                                  \
            _Pragma("unroll")                                                  \
            for (int j = 1; j < TOPK; j++) nt = fminf(nt, lv[j]);              \
            thr[(qq)] = nt;                                                    \
        }                                                                      \
    }                                                                          \
} while (0)

__global__ __launch_bounds__(128, 2)
void retr_kernel(const float* __restrict__ queries,
                 const float* __restrict__ corpus,
                 float* __restrict__ out, int out_size, int n, int nTiles)
{
    extern __shared__ float smem[];
    float* buf = smem;                         // 2 * TILE * WPAD
    float* qsm = buf + 2 * TILE * WPAD;        // EMB * NQ, layout [k][q]
    float* wv  = qsm + EMB * NQ;               // 32 lists * TOPK
    int*   wi  = (int*)(wv + 4 * 8 * TOPK);

    int tid = threadIdx.x;
    int tx  = tid & 31;
    int ty  = tid >> 5;

    // ---- inline query normalization (thread t < 32 handles query t) ----
    if (tid < NQ) {
        const float4* qv = (const float4*)(queries + tid * EMB);
        float ss = 0.f;
        #pragma unroll
        for (int i = 0; i < 32; i++) {
            float4 v = qv[i];
            ss += v.x * v.x + v.y * v.y + v.z * v.z + v.w * v.w;
        }
        float inv = 1.0f / fmaxf(sqrtf(ss), 1e-12f);
        #pragma unroll
        for (int i = 0; i < 32; i++) {
            float4 v = qv[i];
            qsm[(4 * i + 0) * NQ + tid] = v.x * inv;
            qsm[(4 * i + 1) * NQ + tid] = v.y * inv;
            qsm[(4 * i + 2) * NQ + tid] = v.z * inv;
            qsm[(4 * i + 3) * NQ + tid] = v.w * inv;
        }
        #pragma unroll
        for (int s = 0; s < TOPK; s++) { wv[tid * TOPK + s] = NEG_HUGE; wi[tid * TOPK + s] = 0; }
    }
    float thr[8];
    #pragma unroll
    for (int j = 0; j < 8; j++) thr[j] = NEG_HUGE;
    __syncthreads();

    // ---- cp.async staging helper ----
    auto issue = [&](int tile, int bsel) {
        int gbase2 = tile * TILE;
        float* db = buf + bsel * TILE * WPAD;
        #pragma unroll
        for (int i = 0; i < 16; i++) {
            int idx = tid + 128 * i;
            int row = idx >> 5, c4 = idx & 31;
            int g   = gbase2 + row;
            unsigned dst = (unsigned)__cvta_generic_to_shared(db + row * WPAD + c4 * 4);
            const float* src = corpus + (size_t)g * EMB + c4 * 4;
            int sz = (g < n) ? 16 : 0;
            CP_ASYNC16(dst, src, sz);
        }
    };

    // prologue: stage first tile
    int myFirst = blockIdx.x;
    if (myFirst < nTiles) issue(myFirst, 0);
    CP_COMMIT();

    int b = 0;
    for (int tile = myFirst; tile < nTiles; tile += gridDim.x, b ^= 1) {
        int next = tile + gridDim.x;
        if (next < nTiles) issue(next, b ^ 1);
        CP_COMMIT();
        CP_WAIT1();          // tile's own group done; next may be in flight
        __syncthreads();

        int gbase = tile * TILE;
        const float4* sct4 = (const float4*)(buf + b * TILE * WPAD);

        // ---- register-tiled GEMM: 8 queries x 2 rows, packed f32x2 ----
        unsigned long long acc[4][2];
        unsigned long long nacc = 0ull;
        #pragma unroll
        for (int p = 0; p < 4; p++) { acc[p][0] = 0ull; acc[p][1] = 0ull; }

        #pragma unroll
        for (int k4 = 0; k4 < 32; k4++) {
            float4 ca = sct4[tx * W4 + k4];            // row tx
            float4 cb = sct4[(tx + 32) * W4 + k4];     // row tx+32
            float caf[4] = {ca.x, ca.y, ca.z, ca.w};
            float cbf[4] = {cb.x, cb.y, cb.z, cb.w};
            #pragma unroll
            for (int j = 0; j < 4; j++) {
                int k = k4 * 4 + j;
                const ulonglong2* qp = (const ulonglong2*)(qsm + k * NQ + ty * 8);
                ulonglong2 qA = qp[0];   // (q0,q1) (q2,q3)
                ulonglong2 qB = qp[1];   // (q4,q5) (q6,q7)
                unsigned long long cc0, cc1, ncc;
                PACK2(cc0, caf[j], caf[j]);
                PACK2(cc1, cbf[j], cbf[j]);
                PACK2(ncc, caf[j], cbf[j]);
                FMA2(acc[0][0], qA.x, cc0); FMA2(acc[0][1], qA.x, cc1);
                FMA2(acc[1][0], qA.y, cc0); FMA2(acc[1][1], qA.y, cc1);
                FMA2(acc[2][0], qB.x, cc0); FMA2(acc[2][1], qB.x, cc1);
                FMA2(acc[3][0], qB.y, cc0); FMA2(acc[3][1], qB.y, cc1);
                FMA2(nacc, ncc, ncc);                  // row sumsq, both rows
            }
        }

        // ---- epilogue: normalize by corpus norm, top-10 insert ----
        float n0 = __uint_as_float((unsigned)(nacc & 0xffffffffull));
        float n1 = __uint_as_float((unsigned)(nacc >> 32));
        float inv0 = 1.0f / fmaxf(sqrtf(n0), 1e-12f);
        float inv1 = 1.0f / fmaxf(sqrtf(n1), 1e-12f);
        #pragma unroll
        for (int p = 0; p < 4; p++) {
            #pragma unroll
            for (int rr = 0; rr < 2; rr++) {
                float civ = rr ? inv1 : inv0;
                float s0 = __uint_as_float((unsigned)(acc[p][rr] & 0xffffffffull)) * civ;
                float s1 = __uint_as_float((unsigned)(acc[p][rr] >> 32)) * civ;
                INSERT(s0, 2 * p + 0, rr);
                INSERT(s1, 2 * p + 1, rr);
            }
        }
        __syncthreads();   // protect buf[b] before it is re-staged next wrap
    }

    // ---- dump per-warp candidate lists ----
    __syncwarp();
    for (int e = tx; e < 8 * TOPK; e += 32) {
        g_cv[(blockIdx.x * 4 + ty) * 80 + e] = wv[ty * 80 + e];
        g_ci[(blockIdx.x * 4 + ty) * 80 + e] = wi[ty * 80 + e];
    }

    // ---- last block merges ----
    __shared__ unsigned s_last;
    __threadfence();
    if (tid == 0) {
        unsigned old = atomicInc(&g_ctr, NBLK - 1);   // wraps to 0 -> reset for next launch
        s_last = (old == NBLK - 1) ? 1u : 0u;
    }
    __syncthreads();
    if (!s_last) return;
    __threadfence();

    // 4 threads per query scan 296 blocks' candidates
    int q = tid >> 2, part = tid & 2 ? (tid & 3) : (tid & 3); part = tid & 3;
    float lv[TOPK]; int li[TOPK];
    #pragma unroll
    for (int j = 0; j < TOPK; j++) { lv[j] = NEG_HUGE; li[j] = 0x7fffffff; }
    int w = q >> 3, jq = q & 7;
    for (int blk = part; blk < NBLK; blk += 4) {
        int base = (blk * 4 + w) * 80 + jq * TOPK;
        #pragma unroll
        for (int s = 0; s < TOPK; s++) {
            float v = g_cv[base + s]; int gi = g_ci[base + s];
            float mn = lv[0]; int ms = 0;
            #pragma unroll
            for (int j = 1; j < TOPK; j++) if (lv[j] < mn) { mn = lv[j]; ms = j; }
            if (v > mn) { lv[ms] = v; li[ms] = gi; }
        }
    }
    float* mv = buf;                      // reuse tile buffers as scratch
    int*   mi = (int*)(buf + 128 * TOPK);
    #pragma unroll
    for (int j = 0; j < TOPK; j++) { mv[tid * TOPK + j] = lv[j]; mi[tid * TOPK + j] = li[j]; }
    __syncthreads();

    if (part == 0) {                      // tid == q*4
        float l3[TOPK]; int i3[TOPK];
        #pragma unroll
        for (int j = 0; j < TOPK; j++) { l3[j] = NEG_HUGE; i3[j] = 0x7fffffff; }
        for (int t = 0; t < 4 * TOPK; t++) {
            float v = mv[(q * 4) * TOPK + t]; int gi = mi[(q * 4) * TOPK + t];
            float mn = l3[0]; int ms = 0;
            #pragma unroll
            for (int j = 1; j < TOPK; j++) if (l3[j] < mn) { mn = l3[j]; ms = j; }
            if (v > mn) { l3[ms] = v; i3[ms] = gi; }
        }
        // sort desc, tie -> lower index (matches lax.top_k)
        for (int a = 0; a < TOPK; a++) {
            int best = a;
            for (int bb = a + 1; bb < TOPK; bb++)
                if (l3[bb] > l3[best] ||
                    (l3[bb] == l3[best] && i3[bb] < i3[best])) best = bb;
            float tv = l3[a]; l3[a] = l3[best]; l3[best] = tv;
            int   ti = i3[a]; i3[a] = i3[best]; i3[best] = ti;
        }
        if (out_size >= 2 * NQ * TOPK) {
            for (int j = 0; j < TOPK; j++) {
                out[q * TOPK + j] = l3[j];
                out[NQ * TOPK + q * TOPK + j] = (float)i3[j];
            }
        } else {
            for (int j = 0; j < TOPK; j++)
                if (q * TOPK + j < out_size) out[q * TOPK + j] = l3[j];
        }
    }
}

extern "C" void kernel_launch(void* const* d_in, const int* in_sizes, int n_in,
                              void* d_out, int out_size) {
    const float* queries = (const float*)d_in[0];
    const float* corpus  = (const float*)d_in[1];
    int n = in_sizes[1] / EMB;
    int nTiles = (n + TILE - 1) / TILE;

    size_t smemBytes = (size_t)(2 * TILE * WPAD + EMB * NQ + 4 * 8 * TOPK) * sizeof(float)
                     + (size_t)(4 * 8 * TOPK) * sizeof(int);
    cudaFuncSetAttribute(retr_kernel,
                         cudaFuncAttributeMaxDynamicSharedMemorySize, (int)smemBytes);

    retr_kernel<<<NBLK, 128, smemBytes>>>(queries, corpus, (float*)d_out,
                                          out_size, n, nTiles);
}